// round 15
// baseline (speedup 1.0000x reference)
#include <cuda_runtime.h>
#include <cuda_fp16.h>
#include <math.h>
#include <stdint.h>

#define BSC 4
#define N_HEADSC 8
#define N_EDGESC 1024
#define N_NODESC 4096
#define Q_ELEMS (BSC * N_EDGESC * 512)
#define K_ELEMS (BSC * N_NODESC * 512)
#define W_ELEMS (512 * 512)
#define QSCL 0.18033688f   // 0.125 * log2(e)

__device__ __half g_qh[Q_ELEMS];
__device__ __half g_kh[K_ELEMS];
__device__ __half g_Wqh[W_ELEMS], g_Wkh[W_ELEMS], g_Wvh[W_ELEMS];
__device__ __half g_Woh[W_ELEMS], g_Wol[W_ELEMS];
__device__ __half g_Qh[Q_ELEMS];            // row-major, pre-scaled
__device__ __half g_Kh[K_ELEMS];            // [b][h][tile][64x128B] swizzled
__device__ __half g_Vh[K_ELEMS];
__device__ __half g_Ah[Q_ELEMS], g_Al[Q_ELEMS];
__device__ unsigned g_mask[BSC * 128 * N_EDGESC]; // [b][word][edge]

// ---------------------------------------------------------------------------
__device__ __forceinline__ void split2(float a, float b, unsigned& hi, unsigned& lo) {
    __half2 h = __floats2half2_rn(a, b);
    float2 f = __half22float2(h);
    __half2 l = __floats2half2_rn(a - f.x, b - f.y);
    hi = *(unsigned*)&h; lo = *(unsigned*)&l;
}
__device__ __forceinline__ unsigned cvt2(float a, float b) {
    __half2 h = __floats2half2_rn(a, b);
    return *(unsigned*)&h;
}
__device__ __forceinline__ void mma16(float* c, const unsigned* a, const unsigned* b) {
    asm volatile(
        "mma.sync.aligned.m16n8k16.row.col.f32.f16.f16.f32 "
        "{%0,%1,%2,%3},{%4,%5,%6,%7},{%8,%9},{%0,%1,%2,%3};"
        : "+f"(c[0]), "+f"(c[1]), "+f"(c[2]), "+f"(c[3])
        : "r"(a[0]), "r"(a[1]), "r"(a[2]), "r"(a[3]), "r"(b[0]), "r"(b[1]));
}
#define LDSM4(r0,r1,r2,r3,addr) \
    asm volatile("ldmatrix.sync.aligned.m8n8.x4.shared.b16 {%0,%1,%2,%3},[%4];" \
                 : "=r"(r0),"=r"(r1),"=r"(r2),"=r"(r3) : "r"(addr))
#define LDSM4T(r0,r1,r2,r3,addr) \
    asm volatile("ldmatrix.sync.aligned.m8n8.x4.trans.shared.b16 {%0,%1,%2,%3},[%4];" \
                 : "=r"(r0),"=r"(r1),"=r"(r2),"=r"(r3) : "r"(addr))
__device__ __forceinline__ unsigned sptr(const void* p) {
    return (unsigned)__cvta_generic_to_shared(p);
}
__device__ __forceinline__ void cpa16(uint32_t dst, const void* src) {
    asm volatile("cp.async.cg.shared.global [%0], [%1], 16;" :: "r"(dst), "l"(src));
}
#define CPA_COMMIT() asm volatile("cp.async.commit_group;" ::: "memory")
#define CPA_WAIT0()  asm volatile("cp.async.wait_group 0;" ::: "memory")
#define CPA_WAIT1()  asm volatile("cp.async.wait_group 1;" ::: "memory")

__device__ __forceinline__ void bulkcp(uint32_t dst, const void* src, uint32_t bytes, uint32_t bar) {
    asm volatile(
        "cp.async.bulk.shared::cta.global.mbarrier::complete_tx::bytes [%0], [%1], %2, [%3];"
        :: "r"(dst), "l"(src), "r"(bytes), "r"(bar) : "memory");
}
#define MBAR_INIT(mbar, cnt) \
    asm volatile("mbarrier.init.shared.b64 [%0], %1;" :: "r"((uint32_t)(mbar)), "r"((uint32_t)(cnt)) : "memory")
#define MBAR_ARRIVE_TX(mbar, bytes) \
    asm volatile("mbarrier.arrive.expect_tx.shared.b64 _, [%0], %1;" \
                 :: "r"((uint32_t)(mbar)), "r"((uint32_t)(bytes)) : "memory")
#define MBAR_WAIT(mbar, par) do {                                              \
    uint32_t _m = (uint32_t)(mbar), _p = (uint32_t)(par), _d;                  \
    asm volatile("{\n\t.reg .pred p;\n\t"                                      \
        "mbarrier.try_wait.parity.acquire.cta.shared::cta.b64 p, [%1], %2;\n\t"\
        "selp.b32 %0, 1, 0, p;\n\t}" : "=r"(_d) : "r"(_m), "r"(_p) : "memory");\
    if (!_d) {                                                                 \
        asm volatile("{\n\t.reg .pred P1;\n\t"                                 \
            "W%=:\n\t"                                                         \
            "mbarrier.try_wait.parity.acquire.cta.shared::cta.b64 P1, [%0], %1, 0x989680;\n\t" \
            "@P1 bra.uni D%=;\n\tbra.uni W%=;\n\tD%=:\n\t}"                    \
            :: "r"(_m), "r"(_p) : "memory");                                   \
    }                                                                          \
} while (0)

// ---------------------------------------------------------------------------
__global__ void pack_mask_kernel(const int4* __restrict__ inc, unsigned* __restrict__ mask) {
    int tid = blockIdx.x * blockDim.x + threadIdx.x;
    int lane = threadIdx.x & 31;
    int4 v = inc[tid];
    unsigned nib = (v.x != 0 ? 1u : 0u) | (v.y != 0 ? 2u : 0u) |
                   (v.z != 0 ? 4u : 0u) | (v.w != 0 ? 8u : 0u);
    unsigned val = nib << ((lane & 7) * 4);
    val |= __shfl_xor_sync(0xffffffffu, val, 1);
    val |= __shfl_xor_sync(0xffffffffu, val, 2);
    val |= __shfl_xor_sync(0xffffffffu, val, 4);
    if ((lane & 7) == 0) {
        unsigned W = (unsigned)(tid >> 5) * 4u + (unsigned)(lane >> 3);
        unsigned w = W & 127u, be = W >> 7;
        mask[(((be >> 10) * 128u) + w) * 1024u + (be & 1023u)] = val;
    }
}

__global__ void cvt_qk_kernel(
    const float4* __restrict__ xq, const float4* __restrict__ xk,
    char* __restrict__ qh, char* __restrict__ kh)
{
    int i = blockIdx.x * blockDim.x + threadIdx.x;
    const int Q4 = Q_ELEMS / 4;
    const float4* s; char* o; int j; size_t MA;
    if (i < Q4) { s = xq; o = qh; j = i; MA = BSC * N_EDGESC; }
    else        { s = xk; o = kh; j = i - Q4; MA = BSC * N_NODESC; }
    int m = j >> 7, k = (j & 127) * 4;
    float4 v = s[j];
    size_t byte = ((size_t)(k >> 6) * MA + m) * 128 +
                  (((unsigned)(k & 63) * 2) ^ (((unsigned)m & 7u) << 4));
    *(uint2*)(o + byte) = make_uint2(cvt2(v.x, v.y), cvt2(v.z, v.w));
}

__global__ void split_w_kernel(
    const float4* __restrict__ wq, const float4* __restrict__ wk,
    const float4* __restrict__ wv, const float4* __restrict__ wo,
    char* __restrict__ qh, char* __restrict__ kh, char* __restrict__ vh,
    uint2* __restrict__ oh, uint2* __restrict__ ol)
{
    int i = blockIdx.x * blockDim.x + threadIdx.x;
    int which = i >> 16, j = i & 65535;
    if (which == 3) {
        float4 v = wo[j];
        unsigned h0, l0, h1, l1;
        split2(v.x, v.y, h0, l0); split2(v.z, v.w, h1, l1);
        oh[j] = make_uint2(h0, h1); ol[j] = make_uint2(l0, l1);
    } else {
        const float4* s = (which == 0) ? wq : (which == 1) ? wk : wv;
        char* o = (which == 0) ? qh : (which == 1) ? kh : vh;
        float scl = (which == 0) ? QSCL : 1.f;
        int n = j >> 7, k = (j & 127) * 4;
        float4 v = s[j];
        size_t byte = ((size_t)(k >> 6) * 512 + n) * 128 +
                      (((unsigned)(k & 63) * 2) ^ (((unsigned)n & 7u) << 4));
        *(uint2*)(o + byte) = make_uint2(cvt2(v.x * scl, v.y * scl),
                                         cvt2(v.z * scl, v.w * scl));
    }
}

// ---------------------------------------------------------------------------
// Q/K/V projections, single-pass fp16, 3-stage bulk pipeline, smem-staged
// coalesced epilogue. grid (4, 288).
// ---------------------------------------------------------------------------
#define GQ_STAGE 32768u
#define GQ_SMEM (3 * 32768 + 1024 + 64)

__global__ __launch_bounds__(256, 2) void gemm_qkv(
    const char* __restrict__ qh, const char* __restrict__ kh,
    const char* __restrict__ Wqh, const char* __restrict__ Wkh,
    const char* __restrict__ Wvh,
    const float* __restrict__ bq, const float* __restrict__ bk,
    const float* __restrict__ bv,
    __half* __restrict__ Qh, __half* __restrict__ Kh, __half* __restrict__ Vh)
{
    extern __shared__ __align__(16) char raw[];
    char* sm = (char*)((((uintptr_t)raw) + 1023) & ~(uintptr_t)1023);
    const uint32_t sb = sptr(sm);
    const uint32_t barb = sb + 3 * GQ_STAGE;

    const int t = threadIdx.x, lane = t & 31, wid = t >> 5;
    const int g = lane >> 2, q = lane & 3;
    const int wm = wid & 3, wn = wid >> 2;
    const int by = blockIdx.y, n0 = blockIdx.x * 128;

    const char* Ab; const char* Wb; size_t MA; int m0;
    const float* bias; __half* Ch; int isQ = 0;
    if (by < 32)       { Ab = qh; Wb = Wqh; MA = 4096;  m0 = by * 128;         bias = bq; Ch = Qh; isQ = 1; }
    else if (by < 160) { Ab = kh; Wb = Wkh; MA = 16384; m0 = (by - 32) * 128;  bias = bk; Ch = Kh; }
    else               { Ab = kh; Wb = Wvh; MA = 16384; m0 = (by - 160) * 128; bias = bv; Ch = Vh; }

    if (t == 0) { MBAR_INIT(barb, 1); MBAR_INIT(barb + 8, 1); MBAR_INIT(barb + 16, 1); }
    __syncthreads();

    float acc[2][8][4];
#pragma unroll
    for (int mb = 0; mb < 2; mb++)
#pragma unroll
        for (int nb = 0; nb < 8; nb++)
#pragma unroll
            for (int i = 0; i < 4; i++) acc[mb][nb][i] = 0.f;

    const uint32_t laneXor = (uint32_t)((lane & 7) << 4);
    const uint32_t aRow = (uint32_t)((lane & 7) + ((lane >> 3) & 1) * 8);
    const uint32_t aC   = (uint32_t)((lane >> 4) * 16);
    const uint32_t bRow = (uint32_t)((lane & 7) + ((lane >> 4) & 1) * 8);
    const uint32_t bC   = (uint32_t)(((lane >> 3) & 1) * 16);

    if (t == 0) {
#pragma unroll
        for (int p = 0; p < 2; p++) {
            const uint32_t s2 = sb + (uint32_t)p * GQ_STAGE;
            MBAR_ARRIVE_TX(barb + 8 * p, 32768);
            bulkcp(s2,         Ab + ((size_t)p * MA + m0) * 128, 16384, barb + 8 * p);
            bulkcp(s2 + 16384, Wb + ((size_t)p * 512 + n0) * 128, 16384, barb + 8 * p);
        }
    }

#pragma unroll
    for (int ch = 0; ch < 8; ch++) {
        const int st = ch % 3;
        if (ch + 2 < 8 && t == 0) {
            const int st2 = (ch + 2) % 3;
            const uint32_t s2 = sb + (uint32_t)st2 * GQ_STAGE;
            MBAR_ARRIVE_TX(barb + 8 * st2, 32768);
            bulkcp(s2,         Ab + ((size_t)(ch + 2) * MA + m0) * 128, 16384, barb + 8 * st2);
            bulkcp(s2 + 16384, Wb + ((size_t)(ch + 2) * 512 + n0) * 128, 16384, barb + 8 * st2);
        }
        MBAR_WAIT(barb + 8 * st, (ch / 3) & 1);

        const uint32_t stA = sb + (uint32_t)st * GQ_STAGE;
        const uint32_t stW = stA + 16384;
#pragma unroll
        for (int ks = 0; ks < 4; ks++) {
            const uint32_t colA = ((uint32_t)(ks * 32) + aC) ^ laneXor;
            const uint32_t colB = ((uint32_t)(ks * 32) + bC) ^ laneXor;
            unsigned ah[2][4];
#pragma unroll
            for (int mb = 0; mb < 2; mb++)
                LDSM4(ah[mb][0], ah[mb][1], ah[mb][2], ah[mb][3],
                      stA + (uint32_t)((wm * 32 + mb * 16) + aRow) * 128 + colA);
#pragma unroll
            for (int nbp = 0; nbp < 4; nbp++) {
                unsigned bh[4];
                LDSM4(bh[0], bh[1], bh[2], bh[3],
                      stW + (uint32_t)((wn * 64 + nbp * 16) + bRow) * 128 + colB);
#pragma unroll
                for (int mb = 0; mb < 2; mb++) {
                    mma16(acc[mb][2 * nbp], ah[mb], bh);
                    mma16(acc[mb][2 * nbp + 1], ah[mb], bh + 2);
                }
            }
        }
        __syncthreads();
    }

    // epilogue: stage 128x128 fp16 tile in smem (swizzled, conflict-free),
    // then 2048 coalesced uint4 stores.
    const float bscl = isQ ? QSCL : 1.f;
#pragma unroll
    for (int nb = 0; nb < 8; nb++) {
        const int colloc = wn * 64 + nb * 8 + 2 * q;
        float b0 = bias[n0 + colloc] * bscl, b1 = bias[n0 + colloc + 1] * bscl;
#pragma unroll
        for (int mb = 0; mb < 2; mb++) {
#pragma unroll
            for (int half = 0; half < 2; half++) {
                const int rl = wm * 32 + mb * 16 + g + half * 8;
                unsigned hv = half ? cvt2(acc[mb][nb][2] + b0, acc[mb][nb][3] + b1)
                                   : cvt2(acc[mb][nb][0] + b0, acc[mb][nb][1] + b1);
                uint32_t off;
                if (isQ) {
                    off = (uint32_t)rl * 256 + (((uint32_t)colloc * 2) ^ (((uint32_t)rl & 7u) << 4));
                } else {
                    const int bi = (colloc >> 6) * 2 + (rl >> 6);
                    off = (uint32_t)bi * 8192 +
                          ((((uint32_t)(rl & 63)) * 128 + ((uint32_t)(colloc & 63)) * 2)
                           ^ (((uint32_t)rl & 7u) << 4));
                }
                *(unsigned*)(sm + off) = hv;
            }
        }
    }
    __syncthreads();

    if (isQ) {
#pragma unroll
        for (int i = 0; i < 8; i++) {
            const int idx = t + i * 256;
            const int row = idx >> 4, c16 = idx & 15;
            uint4 v = *(uint4*)(sm + row * 256 + (((uint32_t)c16 * 16) ^ (((uint32_t)row & 7u) << 4)));
            *(uint4*)((char*)Ch + ((size_t)(m0 + row) * 512 + n0) * 2 + c16 * 16) = v;
        }
    } else {
        const int bb2 = m0 >> 12, til0 = (m0 >> 6) & 63, hh0 = n0 >> 6;
#pragma unroll
        for (int i = 0; i < 8; i++) {
            const int idx = t + i * 256;
            const int bi = idx >> 9, within = (idx & 511) * 16;
            uint4 v = *(uint4*)(sm + bi * 8192 + within);
            size_t gb = (((size_t)(bb2 * 8 + hh0 + (bi >> 1)) * 64) + til0 + (bi & 1)) * 8192 + within;
            *(uint4*)((char*)Ch + gb) = v;
        }
    }
}

// ---------------------------------------------------------------------------
// O projection (3-pass fp16 split), cp.async path (unchanged)
// ---------------------------------------------------------------------------
#define GEMM_SMEM_P3 (2 * 40960)

__global__ __launch_bounds__(256, 2) void gemm_o(
    const __half* __restrict__ Ahp, const __half* __restrict__ Alp,
    const __half* __restrict__ Whp, const __half* __restrict__ Wlp,
    const float* __restrict__ bias, float* __restrict__ C)
{
    extern __shared__ __align__(16) char gsm[];
    const uint32_t sb = sptr(gsm);
    const int m0 = blockIdx.y * 128, n0 = blockIdx.x * 128;
    const int t = threadIdx.x, lane = t & 31, wid = t >> 5;
    const int g = lane >> 2, q = lane & 3;
    const int wm = wid & 3, wn = wid >> 2;

    float acc[2][8][4];
#pragma unroll
    for (int mb = 0; mb < 2; mb++)
#pragma unroll
        for (int nb = 0; nb < 8; nb++)
#pragma unroll
            for (int i = 0; i < 4; i++) acc[mb][nb][i] = 0.f;

    const unsigned aoff = (((lane & 7) + ((lane >> 3) & 1) * 8) * 40 + (lane >> 4) * 8) * 2
                          + (unsigned)(wm * 32 * 40 * 2);
    const unsigned boff = (((lane & 7) + (lane >> 4) * 8) * 40 + ((lane >> 3) & 1) * 8) * 2
                          + (unsigned)(wn * 64 * 40 * 2);
    const char* gA0 = (const char*)Ahp + (size_t)m0 * 1024;
    const char* gA1 = (const char*)Alp + (size_t)m0 * 1024;
    const char* gB0 = (const char*)Whp + (size_t)n0 * 1024;
    const char* gB1 = (const char*)Wlp + (size_t)n0 * 1024;
    const int lrow = t >> 2, lc = t & 3;

    auto load_chunk = [&](int ch, int st) {
        const uint32_t bufb = sb + (uint32_t)st * 40960u;
        const size_t gc = (size_t)ch * 64 + (size_t)lc * 16;
#pragma unroll
        for (int i = 0; i < 2; i++) {
            const int row = lrow + i * 64;
            const uint32_t so = (uint32_t)row * 80u + (uint32_t)lc * 16u;
            const size_t go = (size_t)row * 1024 + gc;
            cpa16(bufb + so,          gA0 + go);
            cpa16(bufb + 10240 + so,  gA1 + go);
            cpa16(bufb + 20480 + so,  gB0 + go);
            cpa16(bufb + 30720 + so,  gB1 + go);
        }
        CPA_COMMIT();
    };

    load_chunk(0, 0);
    for (int ch = 0; ch < 16; ch++) {
        const int st = ch & 1;
        if (ch + 1 < 16) { load_chunk(ch + 1, (ch + 1) & 1); CPA_WAIT1(); }
        else             { CPA_WAIT0(); }
        __syncthreads();
        const uint32_t bufb = sb + (uint32_t)st * 40960u;
        const uint32_t aB0 = bufb + aoff, aB1 = bufb + 10240 + aoff;
        const uint32_t bB0 = bufb + 20480 + boff, bB1 = bufb + 30720 + boff;
#pragma unroll
        for (int ks = 0; ks < 2; ks++) {
            const unsigned kb = ks * 32;
            unsigned ah[2][4], al[2][4];
#pragma unroll
            for (int mb = 0; mb < 2; mb++) {
                LDSM4(ah[mb][0], ah[mb][1], ah[mb][2], ah[mb][3], aB0 + mb * (16 * 80) + kb);
                LDSM4(al[mb][0], al[mb][1], al[mb][2], al[mb][3], aB1 + mb * (16 * 80) + kb);
            }
#pragma unroll
            for (int nbp = 0; nbp < 4; nbp++) {
                unsigned bh[4], bl[4];
                LDSM4(bh[0], bh[1], bh[2], bh[3], bB0 + nbp * (16 * 80) + kb);
                LDSM4(bl[0], bl[1], bl[2], bl[3], bB1 + nbp * (16 * 80) + kb);
#pragma unroll
                for (int mb = 0; mb < 2; mb++) {
                    mma16(acc[mb][2 * nbp], ah[mb], bh);
                    mma16(acc[mb][2 * nbp], ah[mb], bl);
                    mma16(acc[mb][2 * nbp], al[mb], bh);
                    mma16(acc[mb][2 * nbp + 1], ah[mb], bh + 2);
                    mma16(acc[mb][2 * nbp + 1], ah[mb], bl + 2);
                    mma16(acc[mb][2 * nbp + 1], al[mb], bh + 2);
                }
            }
        }
        __syncthreads();
    }

#pragma unroll
    for (int nb = 0; nb < 8; nb++) {
        int col = n0 + wn * 64 + nb * 8 + 2 * q;
        float b0 = bias[col], b1 = bias[col + 1];
#pragma unroll
        for (int mb = 0; mb < 2; mb++) {
            int r = m0 + wm * 32 + mb * 16 + g;
            *(float2*)(C + (size_t)r * 512 + col) =
                make_float2(acc[mb][nb][0] + b0, acc[mb][nb][1] + b1);
            *(float2*)(C + (size_t)(r + 8) * 512 + col) =
                make_float2(acc[mb][nb][2] + b0, acc[mb][nb][3] + b1);
        }
    }
}

// ---------------------------------------------------------------------------
// Flash attention: 512 threads, 256 edges/CTA, grid (4, 8, 4) = 128 CTAs
// (1 CTA/SM, single wave). 4-stage bulk pipeline (stage 18432 B:
// K 8K + V 8K + mask 2K). S=Q'·Kh; P=ex2.f16x2&mask; l via mma vs ones.
// ---------------------------------------------------------------------------
#define ATT_STAGE2 18432u
#define ATT_SMEM2 (4 * 18432 + 1024 + 64)

__global__ __launch_bounds__(512, 1) void attn_f16(
    const char* __restrict__ Kt, const char* __restrict__ Vt,
    const unsigned* __restrict__ Mk)
{
    extern __shared__ __align__(16) char raw[];
    char* sm = (char*)((((uintptr_t)raw) + 1023) & ~(uintptr_t)1023);
    const uint32_t sb = sptr(sm);
    const uint32_t barb = sb + 4 * ATT_STAGE2;

    const int t = threadIdx.x, lane = t & 31, wid = t >> 5;
    const int g = lane >> 2, q = lane & 3;
    const int b = blockIdx.z, h = blockIdx.y, e0 = blockIdx.x * 256;
    const int R = wid * 16;

    const unsigned* Qhw = (const unsigned*)(g_Qh + ((size_t)(b * N_EDGESC + e0 + R) * 512 + h * 64));
    unsigned qh[4][4];
#pragma unroll
    for (int ks = 0; ks < 4; ks++) {
        int o = 8 * ks + q;
        qh[ks][0] = Qhw[g * 256 + o];       qh[ks][1] = Qhw[(g + 8) * 256 + o];
        qh[ks][2] = Qhw[g * 256 + o + 4];   qh[ks][3] = Qhw[(g + 8) * 256 + o + 4];
    }

    if (t == 0) {
#pragma unroll
        for (int p = 0; p < 4; p++) MBAR_INIT(barb + 8 * p, 1);
    }
    __syncthreads();

    const char* Kb = Kt + (size_t)(b * N_HEADSC + h) * 64 * 8192;
    const char* Vb = Vt + (size_t)(b * N_HEADSC + h) * 64 * 8192;
    const unsigned* Mb = Mk + (size_t)b * 128 * 1024 + e0;

    const uint32_t laneXor = (uint32_t)((lane & 7) << 4);
    const uint32_t kRow = (uint32_t)(((lane & 7) + ((lane >> 4) & 1) * 8) * 128);
    const uint32_t kC   = (uint32_t)(((lane >> 3) & 1) * 16);
    const uint32_t vRow = (uint32_t)(((lane & 7) + ((lane >> 3) & 1) * 8) * 128);
    const uint32_t vC   = (uint32_t)((lane >> 4) * 16);

    float O[8][4];
#pragma unroll
    for (int nb = 0; nb < 8; nb++)
#pragma unroll
        for (int i = 0; i < 4; i++) O[nb][i] = 0.f;
    float lacc[4] = {0.f, 0.f, 0.f, 0.f};
    const unsigned ones2[2] = {0x3C003C00u, 0x3C003C00u};

    if (t == 0) {
#pragma unroll
        for (int p = 0; p < 3; p++) {
            const uint32_t s2 = sb + (uint32_t)p * ATT_STAGE2;
            MBAR_ARRIVE_TX(barb + 8 * p, 18432);
            bulkcp(s2,         Kb + (size_t)p * 8192, 8192, barb + 8 * p);
            bulkcp(s2 + 8192,  Vb + (size_t)p * 8192, 8192, barb + 8 * p);
            bulkcp(s2 + 16384, Mb + (size_t)p * 2048,        1024, barb + 8 * p);
            bulkcp(s2 + 17408, Mb + (size_t)p * 2048 + 1024, 1024, barb + 8 * p);
        }
    }

    for (int it4 = 0; it4 < 16; it4++) {
#pragma unroll
        for (int st = 0; st < 4; st++) {
            const int it = it4 * 4 + st;
            if (it + 3 < 64 && t == 0) {
                const int st2 = (st + 3) & 3;
                const uint32_t s2 = sb + (uint32_t)st2 * ATT_STAGE2;
                MBAR_ARRIVE_TX(barb + 8 * st2, 18432);
                bulkcp(s2,         Kb + (size_t)(it + 3) * 8192, 8192, barb + 8 * st2);
                bulkcp(s2 + 8192,  Vb + (size_t)(it + 3) * 8192, 8192, barb + 8 * st2);
                bulkcp(s2 + 16384, Mb + (size_t)(it + 3) * 2048,        1024, barb + 8 * st2);
                bulkcp(s2 + 17408, Mb + (size_t)(it + 3) * 2048 + 1024, 1024, barb + 8 * st2);
            }
            MBAR_WAIT(barb + 8 * st, (st < 3) ? (it4 & 1) : ((it4 + 1) & 1) ^ 1);

            const uint32_t stAddr = sb + (uint32_t)st * ATT_STAGE2;
            const unsigned* Mp = (const unsigned*)(sm + st * 18432 + 16384);

            float s[8][4];
#pragma unroll
            for (int nb = 0; nb < 8; nb++) {
                s[nb][0] = 0.f; s[nb][1] = 0.f; s[nb][2] = 0.f; s[nb][3] = 0.f;
            }
#pragma unroll
            for (int ks = 0; ks < 4; ks++) {
                const uint32_t colK = ((uint32_t)(ks * 32) + kC) ^ laneXor;
#pragma unroll
                for (int nbp = 0; nbp < 4; nbp++) {
                    unsigned bh[4];
                    LDSM4(bh[0], bh[1], bh[2], bh[3],
                          stAddr + (uint32_t)(nbp * 2048) + kRow + colK);
                    mma16(s[2 * nbp], qh[ks], bh);
                    mma16(s[2 * nbp + 1], qh[ks], bh + 2);
                }
            }

            const unsigned wA0 = Mp[R + g],     wA1 = Mp[256 + R + g];
            const unsigned wB0 = Mp[R + g + 8], wB1 = Mp[256 + R + g + 8];
            unsigned pa[4][4];
#pragma unroll
            for (int nb = 0; nb < 8; nb++) {
                const unsigned w0 = (nb < 4) ? wA0 : wA1;
                const unsigned w1 = (nb < 4) ? wB0 : wB1;
                const int c0 = (nb * 8 + 2 * q) & 31;
                unsigned u01 = cvt2(s[nb][0], s[nb][1]);
                unsigned u23 = cvt2(s[nb][2], s[nb][3]);
                asm("ex2.approx.f16x2 %0, %1;" : "=r"(u01) : "r"(u01));
                asm("ex2.approx.f16x2 %0, %1;" : "=r"(u23) : "r"(u23));
                unsigned mm0 = (((w0 >> c0) & 1u) ? 0xFFFFu : 0u) |
                               (((w0 >> (c0 + 1)) & 1u) ? 0xFFFF0000u : 0u);
                unsigned mm1 = (((w1 >> c0) & 1u) ? 0xFFFFu : 0u) |
                               (((w1 >> (c0 + 1)) & 1u) ? 0xFFFF0000u : 0u);
                u01 &= mm0;
                u23 &= mm1;
                const int jj = nb >> 1, o2 = (nb & 1) << 1;
                pa[jj][o2] = u01;
                pa[jj][o2 + 1] = u23;
            }

#pragma unroll
            for (int j = 0; j < 4; j++) {
                mma16(lacc, pa[j], ones2);
#pragma unroll
                for (int dbp = 0; dbp < 4; dbp++) {
                    const uint32_t colV = ((uint32_t)(dbp * 32) + vC) ^ laneXor;
                    unsigned bh[4];
                    LDSM4T(bh[0], bh[1], bh[2], bh[3],
                           stAddr + 8192 + (uint32_t)(j * 2048) + vRow + colV);
                    mma16(O[2 * dbp], pa[j], bh);
                    mma16(O[2 * dbp + 1], pa[j], bh + 2);
                }
            }
            __syncthreads();
        }
    }

    float inv0 = 1.f / lacc[0], inv1 = 1.f / lacc[2];
    size_t rw0 = ((size_t)(b * N_EDGESC + e0 + R + g) * 512 + h * 64) >> 1;
    size_t rw1 = rw0 + 8 * 256;
    unsigned* Ahw = (unsigned*)g_Ah;
    unsigned* Alw = (unsigned*)g_Al;
#pragma unroll
    for (int nb = 0; nb < 8; nb++) {
        int cw = 4 * nb + q;
        unsigned hh, ll;
        split2(O[nb][0] * inv0, O[nb][1] * inv0, hh, ll);
        Ahw[rw0 + cw] = hh; Alw[rw0 + cw] = ll;
        split2(O[nb][2] * inv1, O[nb][3] * inv1, hh, ll);
        Ahw[rw1 + cw] = hh; Alw[rw1 + cw] = ll;
    }
}

// ---------------------------------------------------------------------------
extern "C" void kernel_launch(void* const* d_in, const int* in_sizes, int n_in,
                              void* d_out, int out_size) {
    (void)in_sizes; (void)n_in; (void)out_size;
    const float* queries = (const float*)d_in[0];
    const float* keys    = (const float*)d_in[1];
    const int*   inc     = (const int*)d_in[2];
    const float* Wq = (const float*)d_in[3];
    const float* bq = (const float*)d_in[4];
    const float* Wk = (const float*)d_in[5];
    const float* bk = (const float*)d_in[6];
    const float* Wv = (const float*)d_in[7];
    const float* bv = (const float*)d_in[8];
    const float* Wo = (const float*)d_in[9];
    const float* bo = (const float*)d_in[10];
    float* out = (float*)d_out;

    __half *qh, *kh, *Wqh, *Wkh, *Wvh, *Woh, *Wol, *Qh, *Kh, *Vh, *Ah, *Al;
    unsigned* pM;
    cudaGetSymbolAddress((void**)&qh, g_qh);
    cudaGetSymbolAddress((void**)&kh, g_kh);
    cudaGetSymbolAddress((void**)&Wqh, g_Wqh);
    cudaGetSymbolAddress((void**)&Wkh, g_Wkh);
    cudaGetSymbolAddress((void**)&Wvh, g_Wvh);
    cudaGetSymbolAddress((void**)&Woh, g_Woh);
    cudaGetSymbolAddress((void**)&Wol, g_Wol);
    cudaGetSymbolAddress((void**)&Qh, g_Qh);
    cudaGetSymbolAddress((void**)&Kh, g_Kh);
    cudaGetSymbolAddress((void**)&Vh, g_Vh);
    cudaGetSymbolAddress((void**)&Ah, g_Ah);
    cudaGetSymbolAddress((void**)&Al, g_Al);
    cudaGetSymbolAddress((void**)&pM, g_mask);

    cudaFuncSetAttribute(gemm_qkv, cudaFuncAttributeMaxDynamicSharedMemorySize, GQ_SMEM);
    cudaFuncSetAttribute(gemm_o, cudaFuncAttributeMaxDynamicSharedMemorySize, GEMM_SMEM_P3);
    cudaFuncSetAttribute(attn_f16, cudaFuncAttributeMaxDynamicSharedMemorySize, ATT_SMEM2);

    cvt_qk_kernel<<<(Q_ELEMS / 4 + K_ELEMS / 4) / 256, 256>>>(
        (const float4*)queries, (const float4*)keys, (char*)qh, (char*)kh);
    split_w_kernel<<<4 * W_ELEMS / 4 / 256, 256>>>(
        (const float4*)Wq, (const float4*)Wk, (const float4*)Wv, (const float4*)Wo,
        (char*)Wqh, (char*)Wkh, (char*)Wvh, (uint2*)Woh, (uint2*)Wol);
    pack_mask_kernel<<<(BSC * N_EDGESC * N_NODESC) / 4 / 256, 256>>>((const int4*)inc, pM);

    gemm_qkv<<<dim3(4, 288), 256, GQ_SMEM>>>(
        (const char*)qh, (const char*)kh, (const char*)Wqh, (const char*)Wkh,
        (const char*)Wvh, bq, bk, bv, Qh, Kh, Vh);

    attn_f16<<<dim3(N_EDGESC / 256, N_HEADSC, BSC), 512, ATT_SMEM2>>>(
        (const char*)Kh, (const char*)Vh, pM);

    gemm_o<<<dim3(4, 32), 256, GEMM_SMEM_P3>>>(Ah, Al, Woh, Wol, bo, out);
}

// round 16
// speedup vs baseline: 1.1131x; 1.1131x over previous
#include <cuda_runtime.h>
#include <cuda_fp16.h>
#include <math.h>
#include <stdint.h>

#define BSC 4
#define N_HEADSC 8
#define N_EDGESC 1024
#define N_NODESC 4096
#define Q_ELEMS (BSC * N_EDGESC * 512)
#define K_ELEMS (BSC * N_NODESC * 512)
#define W_ELEMS (512 * 512)
#define QSCL 0.18033688f   // 0.125 * log2(e)

__device__ __half g_qh[Q_ELEMS];
__device__ __half g_kh[K_ELEMS];
__device__ __half g_Wqh[W_ELEMS], g_Wkh[W_ELEMS], g_Wvh[W_ELEMS];
__device__ __half g_Woh[W_ELEMS];
__device__ __half g_Qh[Q_ELEMS];            // row-major, pre-scaled
__device__ __half g_Kh[K_ELEMS];            // [b][h][tile][64x128B] swizzled
__device__ __half g_Vh[K_ELEMS];
__device__ __half g_Ah[Q_ELEMS];
__device__ unsigned g_mask[BSC * 128 * N_EDGESC]; // [b][word][edge]

// ---------------------------------------------------------------------------
__device__ __forceinline__ unsigned cvt2(float a, float b) {
    __half2 h = __floats2half2_rn(a, b);
    return *(unsigned*)&h;
}
__device__ __forceinline__ void mma16(float* c, const unsigned* a, const unsigned* b) {
    asm volatile(
        "mma.sync.aligned.m16n8k16.row.col.f32.f16.f16.f32 "
        "{%0,%1,%2,%3},{%4,%5,%6,%7},{%8,%9},{%0,%1,%2,%3};"
        : "+f"(c[0]), "+f"(c[1]), "+f"(c[2]), "+f"(c[3])
        : "r"(a[0]), "r"(a[1]), "r"(a[2]), "r"(a[3]), "r"(b[0]), "r"(b[1]));
}
#define LDSM4(r0,r1,r2,r3,addr) \
    asm volatile("ldmatrix.sync.aligned.m8n8.x4.shared.b16 {%0,%1,%2,%3},[%4];" \
                 : "=r"(r0),"=r"(r1),"=r"(r2),"=r"(r3) : "r"(addr))
#define LDSM4T(r0,r1,r2,r3,addr) \
    asm volatile("ldmatrix.sync.aligned.m8n8.x4.trans.shared.b16 {%0,%1,%2,%3},[%4];" \
                 : "=r"(r0),"=r"(r1),"=r"(r2),"=r"(r3) : "r"(addr))
__device__ __forceinline__ unsigned sptr(const void* p) {
    return (unsigned)__cvta_generic_to_shared(p);
}
__device__ __forceinline__ void cpa16(uint32_t dst, const void* src) {
    asm volatile("cp.async.cg.shared.global [%0], [%1], 16;" :: "r"(dst), "l"(src));
}
#define CPA_COMMIT() asm volatile("cp.async.commit_group;" ::: "memory")
#define CPA_WAIT0()  asm volatile("cp.async.wait_group 0;" ::: "memory")
#define CPA_WAIT1()  asm volatile("cp.async.wait_group 1;" ::: "memory")

__device__ __forceinline__ void bulkcp(uint32_t dst, const void* src, uint32_t bytes, uint32_t bar) {
    asm volatile(
        "cp.async.bulk.shared::cta.global.mbarrier::complete_tx::bytes [%0], [%1], %2, [%3];"
        :: "r"(dst), "l"(src), "r"(bytes), "r"(bar) : "memory");
}
#define MBAR_INIT(mbar, cnt) \
    asm volatile("mbarrier.init.shared.b64 [%0], %1;" :: "r"((uint32_t)(mbar)), "r"((uint32_t)(cnt)) : "memory")
#define MBAR_ARRIVE_TX(mbar, bytes) \
    asm volatile("mbarrier.arrive.expect_tx.shared.b64 _, [%0], %1;" \
                 :: "r"((uint32_t)(mbar)), "r"((uint32_t)(bytes)) : "memory")
#define MBAR_WAIT(mbar, par) do {                                              \
    uint32_t _m = (uint32_t)(mbar), _p = (uint32_t)(par), _d;                  \
    asm volatile("{\n\t.reg .pred p;\n\t"                                      \
        "mbarrier.try_wait.parity.acquire.cta.shared::cta.b64 p, [%1], %2;\n\t"\
        "selp.b32 %0, 1, 0, p;\n\t}" : "=r"(_d) : "r"(_m), "r"(_p) : "memory");\
    if (!_d) {                                                                 \
        asm volatile("{\n\t.reg .pred P1;\n\t"                                 \
            "W%=:\n\t"                                                         \
            "mbarrier.try_wait.parity.acquire.cta.shared::cta.b64 P1, [%0], %1, 0x989680;\n\t" \
            "@P1 bra.uni D%=;\n\tbra.uni W%=;\n\tD%=:\n\t}"                    \
            :: "r"(_m), "r"(_p) : "memory");                                   \
    }                                                                          \
} while (0)

// ---------------------------------------------------------------------------
__global__ void pack_mask_kernel(const int4* __restrict__ inc, unsigned* __restrict__ mask) {
    int tid = blockIdx.x * blockDim.x + threadIdx.x;
    int lane = threadIdx.x & 31;
    int4 v = inc[tid];
    unsigned nib = (v.x != 0 ? 1u : 0u) | (v.y != 0 ? 2u : 0u) |
                   (v.z != 0 ? 4u : 0u) | (v.w != 0 ? 8u : 0u);
    unsigned val = nib << ((lane & 7) * 4);
    val |= __shfl_xor_sync(0xffffffffu, val, 1);
    val |= __shfl_xor_sync(0xffffffffu, val, 2);
    val |= __shfl_xor_sync(0xffffffffu, val, 4);
    if ((lane & 7) == 0) {
        unsigned W = (unsigned)(tid >> 5) * 4u + (unsigned)(lane >> 3);
        unsigned w = W & 127u, be = W >> 7;
        mask[(((be >> 10) * 128u) + w) * 1024u + (be & 1023u)] = val;
    }
}

__global__ void cvt_qk_kernel(
    const float4* __restrict__ xq, const float4* __restrict__ xk,
    char* __restrict__ qh, char* __restrict__ kh)
{
    int i = blockIdx.x * blockDim.x + threadIdx.x;
    const int Q4 = Q_ELEMS / 4;
    const float4* s; char* o; int j; size_t MA;
    if (i < Q4) { s = xq; o = qh; j = i; MA = BSC * N_EDGESC; }
    else        { s = xk; o = kh; j = i - Q4; MA = BSC * N_NODESC; }
    int m = j >> 7, k = (j & 127) * 4;
    float4 v = s[j];
    size_t byte = ((size_t)(k >> 6) * MA + m) * 128 +
                  (((unsigned)(k & 63) * 2) ^ (((unsigned)m & 7u) << 4));
    *(uint2*)(o + byte) = make_uint2(cvt2(v.x, v.y), cvt2(v.z, v.w));
}

// weights: Wq (scaled) / Wk / Wv chunk-major swizzled; Wo row-major hi only
__global__ void split_w_kernel(
    const float4* __restrict__ wq, const float4* __restrict__ wk,
    const float4* __restrict__ wv, const float4* __restrict__ wo,
    char* __restrict__ qh, char* __restrict__ kh, char* __restrict__ vh,
    uint2* __restrict__ oh)
{
    int i = blockIdx.x * blockDim.x + threadIdx.x;
    int which = i >> 16, j = i & 65535;
    if (which == 3) {
        float4 v = wo[j];
        oh[j] = make_uint2(cvt2(v.x, v.y), cvt2(v.z, v.w));
    } else {
        const float4* s = (which == 0) ? wq : (which == 1) ? wk : wv;
        char* o = (which == 0) ? qh : (which == 1) ? kh : vh;
        float scl = (which == 0) ? QSCL : 1.f;
        int n = j >> 7, k = (j & 127) * 4;
        float4 v = s[j];
        size_t byte = ((size_t)(k >> 6) * 512 + n) * 128 +
                      (((unsigned)(k & 63) * 2) ^ (((unsigned)n & 7u) << 4));
        *(uint2*)(o + byte) = make_uint2(cvt2(v.x * scl, v.y * scl),
                                         cvt2(v.z * scl, v.w * scl));
    }
}

// ---------------------------------------------------------------------------
// Q/K/V projections: single-pass fp16, 3-stage bulk pipeline, smem-staged
// coalesced epilogue. grid (4, 288).
// ---------------------------------------------------------------------------
#define GQ_STAGE 32768u
#define GQ_SMEM (3 * 32768 + 1024 + 64)

__global__ __launch_bounds__(256, 2) void gemm_qkv(
    const char* __restrict__ qh, const char* __restrict__ kh,
    const char* __restrict__ Wqh, const char* __restrict__ Wkh,
    const char* __restrict__ Wvh,
    const float* __restrict__ bq, const float* __restrict__ bk,
    const float* __restrict__ bv,
    __half* __restrict__ Qh, __half* __restrict__ Kh, __half* __restrict__ Vh)
{
    extern __shared__ __align__(16) char raw[];
    char* sm = (char*)((((uintptr_t)raw) + 1023) & ~(uintptr_t)1023);
    const uint32_t sb = sptr(sm);
    const uint32_t barb = sb + 3 * GQ_STAGE;

    const int t = threadIdx.x, lane = t & 31, wid = t >> 5;
    const int g = lane >> 2, q = lane & 3;
    const int wm = wid & 3, wn = wid >> 2;
    const int by = blockIdx.y, n0 = blockIdx.x * 128;

    const char* Ab; const char* Wb; size_t MA; int m0;
    const float* bias; __half* Ch; int isQ = 0;
    if (by < 32)       { Ab = qh; Wb = Wqh; MA = 4096;  m0 = by * 128;         bias = bq; Ch = Qh; isQ = 1; }
    else if (by < 160) { Ab = kh; Wb = Wkh; MA = 16384; m0 = (by - 32) * 128;  bias = bk; Ch = Kh; }
    else               { Ab = kh; Wb = Wvh; MA = 16384; m0 = (by - 160) * 128; bias = bv; Ch = Vh; }

    if (t == 0) { MBAR_INIT(barb, 1); MBAR_INIT(barb + 8, 1); MBAR_INIT(barb + 16, 1); }
    __syncthreads();

    float acc[2][8][4];
#pragma unroll
    for (int mb = 0; mb < 2; mb++)
#pragma unroll
        for (int nb = 0; nb < 8; nb++)
#pragma unroll
            for (int i = 0; i < 4; i++) acc[mb][nb][i] = 0.f;

    const uint32_t laneXor = (uint32_t)((lane & 7) << 4);
    const uint32_t aRow = (uint32_t)((lane & 7) + ((lane >> 3) & 1) * 8);
    const uint32_t aC   = (uint32_t)((lane >> 4) * 16);
    const uint32_t bRow = (uint32_t)((lane & 7) + ((lane >> 4) & 1) * 8);
    const uint32_t bC   = (uint32_t)(((lane >> 3) & 1) * 16);

    if (t == 0) {
#pragma unroll
        for (int p = 0; p < 2; p++) {
            const uint32_t s2 = sb + (uint32_t)p * GQ_STAGE;
            MBAR_ARRIVE_TX(barb + 8 * p, 32768);
            bulkcp(s2,         Ab + ((size_t)p * MA + m0) * 128, 16384, barb + 8 * p);
            bulkcp(s2 + 16384, Wb + ((size_t)p * 512 + n0) * 128, 16384, barb + 8 * p);
        }
    }

#pragma unroll
    for (int ch = 0; ch < 8; ch++) {
        const int st = ch % 3;
        if (ch + 2 < 8 && t == 0) {
            const int st2 = (ch + 2) % 3;
            const uint32_t s2 = sb + (uint32_t)st2 * GQ_STAGE;
            MBAR_ARRIVE_TX(barb + 8 * st2, 32768);
            bulkcp(s2,         Ab + ((size_t)(ch + 2) * MA + m0) * 128, 16384, barb + 8 * st2);
            bulkcp(s2 + 16384, Wb + ((size_t)(ch + 2) * 512 + n0) * 128, 16384, barb + 8 * st2);
        }
        MBAR_WAIT(barb + 8 * st, (ch / 3) & 1);

        const uint32_t stA = sb + (uint32_t)st * GQ_STAGE;
        const uint32_t stW = stA + 16384;
#pragma unroll
        for (int ks = 0; ks < 4; ks++) {
            const uint32_t colA = ((uint32_t)(ks * 32) + aC) ^ laneXor;
            const uint32_t colB = ((uint32_t)(ks * 32) + bC) ^ laneXor;
            unsigned ah[2][4];
#pragma unroll
            for (int mb = 0; mb < 2; mb++)
                LDSM4(ah[mb][0], ah[mb][1], ah[mb][2], ah[mb][3],
                      stA + (uint32_t)((wm * 32 + mb * 16) + aRow) * 128 + colA);
#pragma unroll
            for (int nbp = 0; nbp < 4; nbp++) {
                unsigned bh[4];
                LDSM4(bh[0], bh[1], bh[2], bh[3],
                      stW + (uint32_t)((wn * 64 + nbp * 16) + bRow) * 128 + colB);
#pragma unroll
                for (int mb = 0; mb < 2; mb++) {
                    mma16(acc[mb][2 * nbp], ah[mb], bh);
                    mma16(acc[mb][2 * nbp + 1], ah[mb], bh + 2);
                }
            }
        }
        __syncthreads();
    }

    // epilogue: stage tile in smem (swizzled), then coalesced uint4 stores
    const float bscl = isQ ? QSCL : 1.f;
#pragma unroll
    for (int nb = 0; nb < 8; nb++) {
        const int colloc = wn * 64 + nb * 8 + 2 * q;
        float b0 = bias[n0 + colloc] * bscl, b1 = bias[n0 + colloc + 1] * bscl;
#pragma unroll
        for (int mb = 0; mb < 2; mb++) {
#pragma unroll
            for (int half = 0; half < 2; half++) {
                const int rl = wm * 32 + mb * 16 + g + half * 8;
                unsigned hv = half ? cvt2(acc[mb][nb][2] + b0, acc[mb][nb][3] + b1)
                                   : cvt2(acc[mb][nb][0] + b0, acc[mb][nb][1] + b1);
                uint32_t off;
                if (isQ) {
                    off = (uint32_t)rl * 256 + (((uint32_t)colloc * 2) ^ (((uint32_t)rl & 7u) << 4));
                } else {
                    const int bi = (colloc >> 6) * 2 + (rl >> 6);
                    off = (uint32_t)bi * 8192 +
                          ((((uint32_t)(rl & 63)) * 128 + ((uint32_t)(colloc & 63)) * 2)
                           ^ (((uint32_t)rl & 7u) << 4));
                }
                *(unsigned*)(sm + off) = hv;
            }
        }
    }
    __syncthreads();

    if (isQ) {
#pragma unroll
        for (int i = 0; i < 8; i++) {
            const int idx = t + i * 256;
            const int row = idx >> 4, c16 = idx & 15;
            uint4 v = *(uint4*)(sm + row * 256 + (((uint32_t)c16 * 16) ^ (((uint32_t)row & 7u) << 4)));
            *(uint4*)((char*)Ch + ((size_t)(m0 + row) * 512 + n0) * 2 + c16 * 16) = v;
        }
    } else {
        const int bb2 = m0 >> 12, til0 = (m0 >> 6) & 63, hh0 = n0 >> 6;
#pragma unroll
        for (int i = 0; i < 8; i++) {
            const int idx = t + i * 256;
            const int bi = idx >> 9, within = (idx & 511) * 16;
            uint4 v = *(uint4*)(sm + bi * 8192 + within);
            size_t gb = (((size_t)(bb2 * 8 + hh0 + (bi >> 1)) * 64) + til0 + (bi & 1)) * 8192 + within;
            *(uint4*)((char*)Ch + gb) = v;
        }
    }
}

// ---------------------------------------------------------------------------
// O projection: single-pass fp16 (error-budget spend), cp.async 2-stage.
// grid (4, 32), fp32 out.
// ---------------------------------------------------------------------------
#define GEMM_O_SMEM (2 * 20480)

__global__ __launch_bounds__(256, 2) void gemm_o(
    const __half* __restrict__ Ahp, const __half* __restrict__ Whp,
    const float* __restrict__ bias, float* __restrict__ C)
{
    extern __shared__ __align__(16) char gsm[];
    const uint32_t sb = sptr(gsm);
    const int m0 = blockIdx.y * 128, n0 = blockIdx.x * 128;
    const int t = threadIdx.x, lane = t & 31, wid = t >> 5;
    const int g = lane >> 2, q = lane & 3;
    const int wm = wid & 3, wn = wid >> 2;

    float acc[2][8][4];
#pragma unroll
    for (int mb = 0; mb < 2; mb++)
#pragma unroll
        for (int nb = 0; nb < 8; nb++)
#pragma unroll
            for (int i = 0; i < 4; i++) acc[mb][nb][i] = 0.f;

    const unsigned aoff = (((lane & 7) + ((lane >> 3) & 1) * 8) * 40 + (lane >> 4) * 8) * 2
                          + (unsigned)(wm * 32 * 40 * 2);
    const unsigned boff = (((lane & 7) + (lane >> 4) * 8) * 40 + ((lane >> 3) & 1) * 8) * 2
                          + (unsigned)(wn * 64 * 40 * 2);
    const char* gA0 = (const char*)Ahp + (size_t)m0 * 1024;
    const char* gB0 = (const char*)Whp + (size_t)n0 * 1024;
    const int lrow = t >> 2, lc = t & 3;

    auto load_chunk = [&](int ch, int st) {
        const uint32_t bufb = sb + (uint32_t)st * 20480u;
        const size_t gc = (size_t)ch * 64 + (size_t)lc * 16;
#pragma unroll
        for (int i = 0; i < 2; i++) {
            const int row = lrow + i * 64;
            const uint32_t so = (uint32_t)row * 80u + (uint32_t)lc * 16u;
            const size_t go = (size_t)row * 1024 + gc;
            cpa16(bufb + so,          gA0 + go);
            cpa16(bufb + 10240 + so,  gB0 + go);
        }
        CPA_COMMIT();
    };

    load_chunk(0, 0);
    for (int ch = 0; ch < 16; ch++) {
        const int st = ch & 1;
        if (ch + 1 < 16) { load_chunk(ch + 1, (ch + 1) & 1); CPA_WAIT1(); }
        else             { CPA_WAIT0(); }
        __syncthreads();
        const uint32_t bufb = sb + (uint32_t)st * 20480u;
        const uint32_t aB0 = bufb + aoff;
        const uint32_t bB0 = bufb + 10240 + boff;
#pragma unroll
        for (int ks = 0; ks < 2; ks++) {
            const unsigned kb = ks * 32;
            unsigned ah[2][4];
#pragma unroll
            for (int mb = 0; mb < 2; mb++)
                LDSM4(ah[mb][0], ah[mb][1], ah[mb][2], ah[mb][3], aB0 + mb * (16 * 80) + kb);
#pragma unroll
            for (int nbp = 0; nbp < 4; nbp++) {
                unsigned bh[4];
                LDSM4(bh[0], bh[1], bh[2], bh[3], bB0 + nbp * (16 * 80) + kb);
#pragma unroll
                for (int mb = 0; mb < 2; mb++) {
                    mma16(acc[mb][2 * nbp], ah[mb], bh);
                    mma16(acc[mb][2 * nbp + 1], ah[mb], bh + 2);
                }
            }
        }
        __syncthreads();
    }

#pragma unroll
    for (int nb = 0; nb < 8; nb++) {
        int col = n0 + wn * 64 + nb * 8 + 2 * q;
        float b0 = bias[col], b1 = bias[col + 1];
#pragma unroll
        for (int mb = 0; mb < 2; mb++) {
            int r = m0 + wm * 32 + mb * 16 + g;
            *(float2*)(C + (size_t)r * 512 + col) =
                make_float2(acc[mb][nb][0] + b0, acc[mb][nb][1] + b1);
            *(float2*)(C + (size_t)(r + 8) * 512 + col) =
                make_float2(acc[mb][nb][2] + b0, acc[mb][nb][3] + b1);
        }
    }
}

// ---------------------------------------------------------------------------
// Flash attention (round-14 proven shape): 256 threads, 2 CTAs/SM,
// grid (8, H, BS), 4-stage bulk pipeline (stage 17408 B: K 8K + V 8K + mask 1K).
// S=Q'·Kh; P=ex2.f16x2&mask; l via mma vs ones; O += P·Vh.
// ---------------------------------------------------------------------------
#define ATT_STAGE2 17408u
#define ATT_SMEM2 (4 * 17408 + 1024 + 64)

__global__ __launch_bounds__(256, 2) void attn_f16(
    const char* __restrict__ Kt, const char* __restrict__ Vt,
    const unsigned* __restrict__ Mk)
{
    extern __shared__ __align__(16) char raw[];
    char* sm = (char*)((((uintptr_t)raw) + 1023) & ~(uintptr_t)1023);
    const uint32_t sb = sptr(sm);
    const uint32_t barb = sb + 4 * ATT_STAGE2;

    const int t = threadIdx.x, lane = t & 31, wid = t >> 5;
    const int g = lane >> 2, q = lane & 3;
    const int b = blockIdx.z, h = blockIdx.y, e0 = blockIdx.x * 128;
    const int R = wid * 16;

    const unsigned* Qhw = (const unsigned*)(g_Qh + ((size_t)(b * N_EDGESC + e0 + R) * 512 + h * 64));
    unsigned qh[4][4];
#pragma unroll
    for (int ks = 0; ks < 4; ks++) {
        int o = 8 * ks + q;
        qh[ks][0] = Qhw[g * 256 + o];       qh[ks][1] = Qhw[(g + 8) * 256 + o];
        qh[ks][2] = Qhw[g * 256 + o + 4];   qh[ks][3] = Qhw[(g + 8) * 256 + o + 4];
    }

    if (t == 0) {
#pragma unroll
        for (int p = 0; p < 4; p++) MBAR_INIT(barb + 8 * p, 1);
    }
    __syncthreads();

    const char* Kb = Kt + (size_t)(b * N_HEADSC + h) * 64 * 8192;
    const char* Vb = Vt + (size_t)(b * N_HEADSC + h) * 64 * 8192;
    const unsigned* Mb = Mk + (size_t)b * 128 * 1024 + e0;

    const uint32_t laneXor = (uint32_t)((lane & 7) << 4);
    const uint32_t kRow = (uint32_t)(((lane & 7) + ((lane >> 4) & 1) * 8) * 128);
    const uint32_t kC   = (uint32_t)(((lane >> 3) & 1) * 16);
    const uint32_t vRow = (uint32_t)(((lane & 7) + ((lane >> 3) & 1) * 8) * 128);
    const uint32_t vC   = (uint32_t)((lane >> 4) * 16);

    float O[8][4];
#pragma unroll
    for (int nb = 0; nb < 8; nb++)
#pragma unroll
        for (int i = 0; i < 4; i++) O[nb][i] = 0.f;
    float lacc[4] = {0.f, 0.f, 0.f, 0.f};
    const unsigned ones2[2] = {0x3C003C00u, 0x3C003C00u};

    if (t == 0) {
#pragma unroll
        for (int p = 0; p < 3; p++) {
            const uint32_t s2 = sb + (uint32_t)p * ATT_STAGE2;
            MBAR_ARRIVE_TX(barb + 8 * p, 17408);
            bulkcp(s2,         Kb + (size_t)p * 8192, 8192, barb + 8 * p);
            bulkcp(s2 + 8192,  Vb + (size_t)p * 8192, 8192, barb + 8 * p);
            bulkcp(s2 + 16384, Mb + (size_t)p * 2048,        512, barb + 8 * p);
            bulkcp(s2 + 16896, Mb + (size_t)p * 2048 + 1024, 512, barb + 8 * p);
        }
    }

    for (int it4 = 0; it4 < 16; it4++) {
#pragma unroll
        for (int st = 0; st < 4; st++) {
            const int it = it4 * 4 + st;
            if (it + 3 < 64 && t == 0) {
                const int st2 = (st + 3) & 3;
                const uint32_t s2 = sb + (uint32_t)st2 * ATT_STAGE2;
                MBAR_ARRIVE_TX(barb + 8 * st2, 17408);
                bulkcp(s2,         Kb + (size_t)(it + 3) * 8192, 8192, barb + 8 * st2);
                bulkcp(s2 + 8192,  Vb + (size_t)(it + 3) * 8192, 8192, barb + 8 * st2);
                bulkcp(s2 + 16384, Mb + (size_t)(it + 3) * 2048,        512, barb + 8 * st2);
                bulkcp(s2 + 16896, Mb + (size_t)(it + 3) * 2048 + 1024, 512, barb + 8 * st2);
            }
            MBAR_WAIT(barb + 8 * st, (st < 3) ? (it4 & 1) : ((it4 + 1) & 1) ^ 1);

            const uint32_t stAddr = sb + (uint32_t)st * ATT_STAGE2;
            const unsigned* Mp = (const unsigned*)(sm + st * 17408 + 16384);

            float s[8][4];
#pragma unroll
            for (int nb = 0; nb < 8; nb++) {
                s[nb][0] = 0.f; s[nb][1] = 0.f; s[nb][2] = 0.f; s[nb][3] = 0.f;
            }
#pragma unroll
            for (int ks = 0; ks < 4; ks++) {
                const uint32_t colK = ((uint32_t)(ks * 32) + kC) ^ laneXor;
#pragma unroll
                for (int nbp = 0; nbp < 4; nbp++) {
                    unsigned bh[4];
                    LDSM4(bh[0], bh[1], bh[2], bh[3],
                          stAddr + (uint32_t)(nbp * 2048) + kRow + colK);
                    mma16(s[2 * nbp], qh[ks], bh);
                    mma16(s[2 * nbp + 1], qh[ks], bh + 2);
                }
            }

            const unsigned wA0 = Mp[R + g],     wA1 = Mp[128 + R + g];
            const unsigned wB0 = Mp[R + g + 8], wB1 = Mp[128 + R + g + 8];
            unsigned pa[4][4];
#pragma unroll
            for (int nb = 0; nb < 8; nb++) {
                const unsigned w0 = (nb < 4) ? wA0 : wA1;
                const unsigned w1 = (nb < 4) ? wB0 : wB1;
                const int c0 = (nb * 8 + 2 * q) & 31;
                unsigned u01 = cvt2(s[nb][0], s[nb][1]);
                unsigned u23 = cvt2(s[nb][2], s[nb][3]);
                asm("ex2.approx.f16x2 %0, %1;" : "=r"(u01) : "r"(u01));
                asm("ex2.approx.f16x2 %0, %1;" : "=r"(u23) : "r"(u23));
                unsigned mm0 = (((w0 >> c0) & 1u) ? 0xFFFFu : 0u) |
                               (((w0 >> (c0 + 1)) & 1u) ? 0xFFFF0000u : 0u);
                unsigned mm1 = (((w1 >> c0) & 1u) ? 0xFFFFu : 0u) |
                               (((w1 >> (c0 + 1)) & 1u) ? 0xFFFF0000u : 0u);
                u01 &= mm0;
                u23 &= mm1;
                const int jj = nb >> 1, o2 = (nb & 1) << 1;
                pa[jj][o2] = u01;
                pa[jj][o2 + 1] = u23;
            }

#pragma unroll
            for (int j = 0; j < 4; j++) {
                mma16(lacc, pa[j], ones2);
#pragma unroll
                for (int dbp = 0; dbp < 4; dbp++) {
                    const uint32_t colV = ((uint32_t)(dbp * 32) + vC) ^ laneXor;
                    unsigned bh[4];
                    LDSM4T(bh[0], bh[1], bh[2], bh[3],
                           stAddr + 8192 + (uint32_t)(j * 2048) + vRow + colV);
                    mma16(O[2 * dbp], pa[j], bh);
                    mma16(O[2 * dbp + 1], pa[j], bh + 2);
                }
            }
            __syncthreads();
        }
    }

    float inv0 = 1.f / lacc[0], inv1 = 1.f / lacc[2];
    size_t rw0 = ((size_t)(b * N_EDGESC + e0 + R + g) * 512 + h * 64) >> 1;
    size_t rw1 = rw0 + 8 * 256;
    unsigned* Ahw = (unsigned*)g_Ah;
#pragma unroll
    for (int nb = 0; nb < 8; nb++) {
        int cw = 4 * nb + q;
        Ahw[rw0 + cw] = cvt2(O[nb][0] * inv0, O[nb][1] * inv0);
        Ahw[rw1 + cw] = cvt2(O[nb][2] * inv1, O[nb][3] * inv1);
    }
}

// ---------------------------------------------------------------------------
extern "C" void kernel_launch(void* const* d_in, const int* in_sizes, int n_in,
                              void* d_out, int out_size) {
    (void)in_sizes; (void)n_in; (void)out_size;
    const float* queries = (const float*)d_in[0];
    const float* keys    = (const float*)d_in[1];
    const int*   inc     = (const int*)d_in[2];
    const float* Wq = (const float*)d_in[3];
    const float* bq = (const float*)d_in[4];
    const float* Wk = (const float*)d_in[5];
    const float* bk = (const float*)d_in[6];
    const float* Wv = (const float*)d_in[7];
    const float* bv = (const float*)d_in[8];
    const float* Wo = (const float*)d_in[9];
    const float* bo = (const float*)d_in[10];
    float* out = (float*)d_out;

    __half *qh, *kh, *Wqh, *Wkh, *Wvh, *Woh, *Qh, *Kh, *Vh, *Ah;
    unsigned* pM;
    cudaGetSymbolAddress((void**)&qh, g_qh);
    cudaGetSymbolAddress((void**)&kh, g_kh);
    cudaGetSymbolAddress((void**)&Wqh, g_Wqh);
    cudaGetSymbolAddress((void**)&Wkh, g_Wkh);
    cudaGetSymbolAddress((void**)&Wvh, g_Wvh);
    cudaGetSymbolAddress((void**)&Woh, g_Woh);
    cudaGetSymbolAddress((void**)&Qh, g_Qh);
    cudaGetSymbolAddress((void**)&Kh, g_Kh);
    cudaGetSymbolAddress((void**)&Vh, g_Vh);
    cudaGetSymbolAddress((void**)&Ah, g_Ah);
    cudaGetSymbolAddress((void**)&pM, g_mask);

    cudaFuncSetAttribute(gemm_qkv, cudaFuncAttributeMaxDynamicSharedMemorySize, GQ_SMEM);
    cudaFuncSetAttribute(gemm_o, cudaFuncAttributeMaxDynamicSharedMemorySize, GEMM_O_SMEM);
    cudaFuncSetAttribute(attn_f16, cudaFuncAttributeMaxDynamicSharedMemorySize, ATT_SMEM2);

    cvt_qk_kernel<<<(Q_ELEMS / 4 + K_ELEMS / 4) / 256, 256>>>(
        (const float4*)queries, (const float4*)keys, (char*)qh, (char*)kh);
    split_w_kernel<<<4 * W_ELEMS / 4 / 256, 256>>>(
        (const float4*)Wq, (const float4*)Wk, (const float4*)Wv, (const float4*)Wo,
        (char*)Wqh, (char*)Wkh, (char*)Wvh, (uint2*)Woh);
    pack_mask_kernel<<<(BSC * N_EDGESC * N_NODESC) / 4 / 256, 256>>>((const int4*)inc, pM);

    gemm_qkv<<<dim3(4, 288), 256, GQ_SMEM>>>(
        (const char*)qh, (const char*)kh, (const char*)Wqh, (const char*)Wkh,
        (const char*)Wvh, bq, bk, bv, Qh, Kh, Vh);

    attn_f16<<<dim3(N_EDGESC / 128, N_HEADSC, BSC), 256, ATT_SMEM2>>>(
        (const char*)Kh, (const char*)Vh, pM);

    gemm_o<<<dim3(4, 32), 256, GEMM_O_SMEM>>>(Ah, Woh, bo, out);
}

// round 17
// speedup vs baseline: 1.1622x; 1.0441x over previous
#include <cuda_runtime.h>
#include <cuda_fp16.h>
#include <math.h>
#include <stdint.h>

#define BSC 4
#define N_HEADSC 8
#define N_EDGESC 1024
#define N_NODESC 4096
#define Q_ELEMS (BSC * N_EDGESC * 512)
#define K_ELEMS (BSC * N_NODESC * 512)
#define W_ELEMS (512 * 512)
#define QSCL 0.18033688f   // 0.125 * log2(e)

__device__ __half g_qh[Q_ELEMS];
__device__ __half g_kh[K_ELEMS];
__device__ __half g_Wqh[W_ELEMS], g_Wkh[W_ELEMS], g_Wvh[W_ELEMS];
__device__ __half g_Woh[W_ELEMS];
__device__ __half g_Qh[Q_ELEMS];            // row-major, pre-scaled
__device__ __half g_Kh[K_ELEMS];            // [b][h][tile][64x128B] swizzled
__device__ __half g_Vh[K_ELEMS];
__device__ __half g_Ah[Q_ELEMS];
__device__ unsigned g_mask[BSC * 128 * N_EDGESC]; // [b][word][edge]

// ---------------------------------------------------------------------------
__device__ __forceinline__ unsigned cvt2(float a, float b) {
    __half2 h = __floats2half2_rn(a, b);
    return *(unsigned*)&h;
}
__device__ __forceinline__ void mma16(float* c, const unsigned* a, const unsigned* b) {
    asm volatile(
        "mma.sync.aligned.m16n8k16.row.col.f32.f16.f16.f32 "
        "{%0,%1,%2,%3},{%4,%5,%6,%7},{%8,%9},{%0,%1,%2,%3};"
        : "+f"(c[0]), "+f"(c[1]), "+f"(c[2]), "+f"(c[3])
        : "r"(a[0]), "r"(a[1]), "r"(a[2]), "r"(a[3]), "r"(b[0]), "r"(b[1]));
}
#define LDSM4(r0,r1,r2,r3,addr) \
    asm volatile("ldmatrix.sync.aligned.m8n8.x4.shared.b16 {%0,%1,%2,%3},[%4];" \
                 : "=r"(r0),"=r"(r1),"=r"(r2),"=r"(r3) : "r"(addr))
#define LDSM4T(r0,r1,r2,r3,addr) \
    asm volatile("ldmatrix.sync.aligned.m8n8.x4.trans.shared.b16 {%0,%1,%2,%3},[%4];" \
                 : "=r"(r0),"=r"(r1),"=r"(r2),"=r"(r3) : "r"(addr))
__device__ __forceinline__ unsigned sptr(const void* p) {
    return (unsigned)__cvta_generic_to_shared(p);
}
__device__ __forceinline__ void cpa16(uint32_t dst, const void* src) {
    asm volatile("cp.async.cg.shared.global [%0], [%1], 16;" :: "r"(dst), "l"(src));
}
#define CPA_COMMIT() asm volatile("cp.async.commit_group;" ::: "memory")
#define CPA_WAIT0()  asm volatile("cp.async.wait_group 0;" ::: "memory")
#define CPA_WAIT1()  asm volatile("cp.async.wait_group 1;" ::: "memory")

__device__ __forceinline__ void bulkcp(uint32_t dst, const void* src, uint32_t bytes, uint32_t bar) {
    asm volatile(
        "cp.async.bulk.shared::cta.global.mbarrier::complete_tx::bytes [%0], [%1], %2, [%3];"
        :: "r"(dst), "l"(src), "r"(bytes), "r"(bar) : "memory");
}
#define MBAR_INIT(mbar, cnt) \
    asm volatile("mbarrier.init.shared.b64 [%0], %1;" :: "r"((uint32_t)(mbar)), "r"((uint32_t)(cnt)) : "memory")
#define MBAR_ARRIVE_TX(mbar, bytes) \
    asm volatile("mbarrier.arrive.expect_tx.shared.b64 _, [%0], %1;" \
                 :: "r"((uint32_t)(mbar)), "r"((uint32_t)(bytes)) : "memory")
#define MBAR_WAIT(mbar, par) do {                                              \
    uint32_t _m = (uint32_t)(mbar), _p = (uint32_t)(par), _d;                  \
    asm volatile("{\n\t.reg .pred p;\n\t"                                      \
        "mbarrier.try_wait.parity.acquire.cta.shared::cta.b64 p, [%1], %2;\n\t"\
        "selp.b32 %0, 1, 0, p;\n\t}" : "=r"(_d) : "r"(_m), "r"(_p) : "memory");\
    if (!_d) {                                                                 \
        asm volatile("{\n\t.reg .pred P1;\n\t"                                 \
            "W%=:\n\t"                                                         \
            "mbarrier.try_wait.parity.acquire.cta.shared::cta.b64 P1, [%0], %1, 0x989680;\n\t" \
            "@P1 bra.uni D%=;\n\tbra.uni W%=;\n\tD%=:\n\t}"                    \
            :: "r"(_m), "r"(_p) : "memory");                                   \
    }                                                                          \
} while (0)

// ---------------------------------------------------------------------------
// merged prologue: cvt_qk (blocks 0..10239), split_w (10240..11263),
// pack_mask (11264..19455, 8 elems/thread)
// ---------------------------------------------------------------------------
#define PREP_CVT_BLOCKS 10240
#define PREP_W_BLOCKS 1024
#define PREP_PACK_BLOCKS 8192
#define PREP_BLOCKS (PREP_CVT_BLOCKS + PREP_W_BLOCKS + PREP_PACK_BLOCKS)

__global__ void prep_kernel(
    const float4* __restrict__ xq, const float4* __restrict__ xk,
    const float4* __restrict__ wq, const float4* __restrict__ wk,
    const float4* __restrict__ wv, const float4* __restrict__ wo,
    const int4* __restrict__ inc,
    char* __restrict__ qh, char* __restrict__ kh,
    char* __restrict__ Wqh, char* __restrict__ Wkh, char* __restrict__ Wvh,
    uint2* __restrict__ Woh, unsigned* __restrict__ mask)
{
    const int blk = blockIdx.x, tid = threadIdx.x;
    if (blk < PREP_CVT_BLOCKS) {
        // queries + keys -> fp16 hi, chunk-major swizzled [ch][m][64]
        int i = blk * 256 + tid;
        const int Q4 = Q_ELEMS / 4;
        const float4* s; char* o; int j; size_t MA;
        if (i < Q4) { s = xq; o = qh; j = i; MA = BSC * N_EDGESC; }
        else        { s = xk; o = kh; j = i - Q4; MA = BSC * N_NODESC; }
        int m = j >> 7, k = (j & 127) * 4;
        float4 v = s[j];
        size_t byte = ((size_t)(k >> 6) * MA + m) * 128 +
                      (((unsigned)(k & 63) * 2) ^ (((unsigned)m & 7u) << 4));
        *(uint2*)(o + byte) = make_uint2(cvt2(v.x, v.y), cvt2(v.z, v.w));
    } else if (blk < PREP_CVT_BLOCKS + PREP_W_BLOCKS) {
        // weights: Wq (scaled) / Wk / Wv chunk-major swizzled; Wo row-major
        int i = (blk - PREP_CVT_BLOCKS) * 256 + tid;
        int which = i >> 16, j = i & 65535;
        if (which == 3) {
            float4 v = wo[j];
            Woh[j] = make_uint2(cvt2(v.x, v.y), cvt2(v.z, v.w));
        } else {
            const float4* s = (which == 0) ? wq : (which == 1) ? wk : wv;
            char* o = (which == 0) ? Wqh : (which == 1) ? Wkh : Wvh;
            float scl = (which == 0) ? QSCL : 1.f;
            int n = j >> 7, k = (j & 127) * 4;
            float4 v = s[j];
            size_t byte = ((size_t)(k >> 6) * 512 + n) * 128 +
                          (((unsigned)(k & 63) * 2) ^ (((unsigned)n & 7u) << 4));
            *(uint2*)(o + byte) = make_uint2(cvt2(v.x * scl, v.y * scl),
                                             cvt2(v.z * scl, v.w * scl));
        }
    } else {
        // pack incidence -> bitmask (transposed), 8 elems/thread
        int gid = (blk - PREP_CVT_BLOCKS - PREP_W_BLOCKS) * 256 + tid;
        int lane = tid & 31;
        const int4* p = inc + (size_t)gid * 2;
        int4 a = p[0], b = p[1];
        unsigned byte = (a.x != 0 ? 1u : 0u) | (a.y != 0 ? 2u : 0u) |
                        (a.z != 0 ? 4u : 0u) | (a.w != 0 ? 8u : 0u) |
                        (b.x != 0 ? 16u : 0u) | (b.y != 0 ? 32u : 0u) |
                        (b.z != 0 ? 64u : 0u) | (b.w != 0 ? 128u : 0u);
        unsigned val = byte << ((lane & 3) * 8);
        val |= __shfl_xor_sync(0xffffffffu, val, 1);
        val |= __shfl_xor_sync(0xffffffffu, val, 2);
        if ((lane & 3) == 0) {
            unsigned W = (unsigned)gid >> 2;
            unsigned w = W & 127u, be = W >> 7;
            mask[(((be >> 10) * 128u) + w) * 1024u + (be & 1023u)] = val;
        }
    }
}

// ---------------------------------------------------------------------------
// Q/K/V projections: single-pass fp16, 3-stage bulk pipeline, smem-staged
// coalesced epilogue. grid (4, 288).
// ---------------------------------------------------------------------------
#define GQ_STAGE 32768u
#define GQ_SMEM (3 * 32768 + 1024 + 64)

__global__ __launch_bounds__(256, 2) void gemm_qkv(
    const char* __restrict__ qh, const char* __restrict__ kh,
    const char* __restrict__ Wqh, const char* __restrict__ Wkh,
    const char* __restrict__ Wvh,
    const float* __restrict__ bq, const float* __restrict__ bk,
    const float* __restrict__ bv,
    __half* __restrict__ Qh, __half* __restrict__ Kh, __half* __restrict__ Vh)
{
    extern __shared__ __align__(16) char raw[];
    char* sm = (char*)((((uintptr_t)raw) + 1023) & ~(uintptr_t)1023);
    const uint32_t sb = sptr(sm);
    const uint32_t barb = sb + 3 * GQ_STAGE;

    const int t = threadIdx.x, lane = t & 31, wid = t >> 5;
    const int g = lane >> 2, q = lane & 3;
    const int wm = wid & 3, wn = wid >> 2;
    const int by = blockIdx.y, n0 = blockIdx.x * 128;

    const char* Ab; const char* Wb; size_t MA; int m0;
    const float* bias; __half* Ch; int isQ = 0;
    if (by < 32)       { Ab = qh; Wb = Wqh; MA = 4096;  m0 = by * 128;         bias = bq; Ch = Qh; isQ = 1; }
    else if (by < 160) { Ab = kh; Wb = Wkh; MA = 16384; m0 = (by - 32) * 128;  bias = bk; Ch = Kh; }
    else               { Ab = kh; Wb = Wvh; MA = 16384; m0 = (by - 160) * 128; bias = bv; Ch = Vh; }

    if (t == 0) { MBAR_INIT(barb, 1); MBAR_INIT(barb + 8, 1); MBAR_INIT(barb + 16, 1); }
    __syncthreads();

    float acc[2][8][4];
#pragma unroll
    for (int mb = 0; mb < 2; mb++)
#pragma unroll
        for (int nb = 0; nb < 8; nb++)
#pragma unroll
            for (int i = 0; i < 4; i++) acc[mb][nb][i] = 0.f;

    const uint32_t laneXor = (uint32_t)((lane & 7) << 4);
    const uint32_t aRow = (uint32_t)((lane & 7) + ((lane >> 3) & 1) * 8);
    const uint32_t aC   = (uint32_t)((lane >> 4) * 16);
    const uint32_t bRow = (uint32_t)((lane & 7) + ((lane >> 4) & 1) * 8);
    const uint32_t bC   = (uint32_t)(((lane >> 3) & 1) * 16);

    if (t == 0) {
#pragma unroll
        for (int p = 0; p < 2; p++) {
            const uint32_t s2 = sb + (uint32_t)p * GQ_STAGE;
            MBAR_ARRIVE_TX(barb + 8 * p, 32768);
            bulkcp(s2,         Ab + ((size_t)p * MA + m0) * 128, 16384, barb + 8 * p);
            bulkcp(s2 + 16384, Wb + ((size_t)p * 512 + n0) * 128, 16384, barb + 8 * p);
        }
    }

#pragma unroll
    for (int ch = 0; ch < 8; ch++) {
        const int st = ch % 3;
        if (ch + 2 < 8 && t == 0) {
            const int st2 = (ch + 2) % 3;
            const uint32_t s2 = sb + (uint32_t)st2 * GQ_STAGE;
            MBAR_ARRIVE_TX(barb + 8 * st2, 32768);
            bulkcp(s2,         Ab + ((size_t)(ch + 2) * MA + m0) * 128, 16384, barb + 8 * st2);
            bulkcp(s2 + 16384, Wb + ((size_t)(ch + 2) * 512 + n0) * 128, 16384, barb + 8 * st2);
        }
        MBAR_WAIT(barb + 8 * st, (ch / 3) & 1);

        const uint32_t stA = sb + (uint32_t)st * GQ_STAGE;
        const uint32_t stW = stA + 16384;
#pragma unroll
        for (int ks = 0; ks < 4; ks++) {
            const uint32_t colA = ((uint32_t)(ks * 32) + aC) ^ laneXor;
            const uint32_t colB = ((uint32_t)(ks * 32) + bC) ^ laneXor;
            unsigned ah[2][4];
#pragma unroll
            for (int mb = 0; mb < 2; mb++)
                LDSM4(ah[mb][0], ah[mb][1], ah[mb][2], ah[mb][3],
                      stA + (uint32_t)((wm * 32 + mb * 16) + aRow) * 128 + colA);
#pragma unroll
            for (int nbp = 0; nbp < 4; nbp++) {
                unsigned bh[4];
                LDSM4(bh[0], bh[1], bh[2], bh[3],
                      stW + (uint32_t)((wn * 64 + nbp * 16) + bRow) * 128 + colB);
#pragma unroll
                for (int mb = 0; mb < 2; mb++) {
                    mma16(acc[mb][2 * nbp], ah[mb], bh);
                    mma16(acc[mb][2 * nbp + 1], ah[mb], bh + 2);
                }
            }
        }
        __syncthreads();
    }

    // epilogue: stage tile in smem (swizzled), then coalesced uint4 stores
    const float bscl = isQ ? QSCL : 1.f;
#pragma unroll
    for (int nb = 0; nb < 8; nb++) {
        const int colloc = wn * 64 + nb * 8 + 2 * q;
        float b0 = bias[n0 + colloc] * bscl, b1 = bias[n0 + colloc + 1] * bscl;
#pragma unroll
        for (int mb = 0; mb < 2; mb++) {
#pragma unroll
            for (int half = 0; half < 2; half++) {
                const int rl = wm * 32 + mb * 16 + g + half * 8;
                unsigned hv = half ? cvt2(acc[mb][nb][2] + b0, acc[mb][nb][3] + b1)
                                   : cvt2(acc[mb][nb][0] + b0, acc[mb][nb][1] + b1);
                uint32_t off;
                if (isQ) {
                    off = (uint32_t)rl * 256 + (((uint32_t)colloc * 2) ^ (((uint32_t)rl & 7u) << 4));
                } else {
                    const int bi = (colloc >> 6) * 2 + (rl >> 6);
                    off = (uint32_t)bi * 8192 +
                          ((((uint32_t)(rl & 63)) * 128 + ((uint32_t)(colloc & 63)) * 2)
                           ^ (((uint32_t)rl & 7u) << 4));
                }
                *(unsigned*)(sm + off) = hv;
            }
        }
    }
    __syncthreads();

    if (isQ) {
#pragma unroll
        for (int i = 0; i < 8; i++) {
            const int idx = t + i * 256;
            const int row = idx >> 4, c16 = idx & 15;
            uint4 v = *(uint4*)(sm + row * 256 + (((uint32_t)c16 * 16) ^ (((uint32_t)row & 7u) << 4)));
            *(uint4*)((char*)Ch + ((size_t)(m0 + row) * 512 + n0) * 2 + c16 * 16) = v;
        }
    } else {
        const int bb2 = m0 >> 12, til0 = (m0 >> 6) & 63, hh0 = n0 >> 6;
#pragma unroll
        for (int i = 0; i < 8; i++) {
            const int idx = t + i * 256;
            const int bi = idx >> 9, within = (idx & 511) * 16;
            uint4 v = *(uint4*)(sm + bi * 8192 + within);
            size_t gb = (((size_t)(bb2 * 8 + hh0 + (bi >> 1)) * 64) + til0 + (bi & 1)) * 8192 + within;
            *(uint4*)((char*)Ch + gb) = v;
        }
    }
}

// ---------------------------------------------------------------------------
// O projection: single-pass fp16, cp.async 2-stage. grid (4, 32), fp32 out.
// ---------------------------------------------------------------------------
#define GEMM_O_SMEM (2 * 20480)

__global__ __launch_bounds__(256, 2) void gemm_o(
    const __half* __restrict__ Ahp, const __half* __restrict__ Whp,
    const float* __restrict__ bias, float* __restrict__ C)
{
    extern __shared__ __align__(16) char gsm[];
    const uint32_t sb = sptr(gsm);
    const int m0 = blockIdx.y * 128, n0 = blockIdx.x * 128;
    const int t = threadIdx.x, lane = t & 31, wid = t >> 5;
    const int g = lane >> 2, q = lane & 3;
    const int wm = wid & 3, wn = wid >> 2;

    float acc[2][8][4];
#pragma unroll
    for (int mb = 0; mb < 2; mb++)
#pragma unroll
        for (int nb = 0; nb < 8; nb++)
#pragma unroll
            for (int i = 0; i < 4; i++) acc[mb][nb][i] = 0.f;

    const unsigned aoff = (((lane & 7) + ((lane >> 3) & 1) * 8) * 40 + (lane >> 4) * 8) * 2
                          + (unsigned)(wm * 32 * 40 * 2);
    const unsigned boff = (((lane & 7) + (lane >> 4) * 8) * 40 + ((lane >> 3) & 1) * 8) * 2
                          + (unsigned)(wn * 64 * 40 * 2);
    const char* gA0 = (const char*)Ahp + (size_t)m0 * 1024;
    const char* gB0 = (const char*)Whp + (size_t)n0 * 1024;
    const int lrow = t >> 2, lc = t & 3;

    auto load_chunk = [&](int ch, int st) {
        const uint32_t bufb = sb + (uint32_t)st * 20480u;
        const size_t gc = (size_t)ch * 64 + (size_t)lc * 16;
#pragma unroll
        for (int i = 0; i < 2; i++) {
            const int row = lrow + i * 64;
            const uint32_t so = (uint32_t)row * 80u + (uint32_t)lc * 16u;
            const size_t go = (size_t)row * 1024 + gc;
            cpa16(bufb + so,          gA0 + go);
            cpa16(bufb + 10240 + so,  gB0 + go);
        }
        CPA_COMMIT();
    };

    load_chunk(0, 0);
    for (int ch = 0; ch < 16; ch++) {
        const int st = ch & 1;
        if (ch + 1 < 16) { load_chunk(ch + 1, (ch + 1) & 1); CPA_WAIT1(); }
        else             { CPA_WAIT0(); }
        __syncthreads();
        const uint32_t bufb = sb + (uint32_t)st * 20480u;
        const uint32_t aB0 = bufb + aoff;
        const uint32_t bB0 = bufb + 10240 + boff;
#pragma unroll
        for (int ks = 0; ks < 2; ks++) {
            const unsigned kb = ks * 32;
            unsigned ah[2][4];
#pragma unroll
            for (int mb = 0; mb < 2; mb++)
                LDSM4(ah[mb][0], ah[mb][1], ah[mb][2], ah[mb][3], aB0 + mb * (16 * 80) + kb);
#pragma unroll
            for (int nbp = 0; nbp < 4; nbp++) {
                unsigned bh[4];
                LDSM4(bh[0], bh[1], bh[2], bh[3], bB0 + nbp * (16 * 80) + kb);
#pragma unroll
                for (int mb = 0; mb < 2; mb++) {
                    mma16(acc[mb][2 * nbp], ah[mb], bh);
                    mma16(acc[mb][2 * nbp + 1], ah[mb], bh + 2);
                }
            }
        }
        __syncthreads();
    }

#pragma unroll
    for (int nb = 0; nb < 8; nb++) {
        int col = n0 + wn * 64 + nb * 8 + 2 * q;
        float b0 = bias[col], b1 = bias[col + 1];
#pragma unroll
        for (int mb = 0; mb < 2; mb++) {
            int r = m0 + wm * 32 + mb * 16 + g;
            *(float2*)(C + (size_t)r * 512 + col) =
                make_float2(acc[mb][nb][0] + b0, acc[mb][nb][1] + b1);
            *(float2*)(C + (size_t)(r + 8) * 512 + col) =
                make_float2(acc[mb][nb][2] + b0, acc[mb][nb][3] + b1);
        }
    }
}

// ---------------------------------------------------------------------------
// Flash attention: 256 threads, 2 CTAs/SM, grid (8, H, BS), 4-stage bulk
// pipeline (stage 17408 B: K 8K + V 8K + mask 1K).
// S=Q'·Kh; P=ex2.f16x2&mask; l via mma vs ones; O += P·Vh.
// ---------------------------------------------------------------------------
#define ATT_STAGE2 17408u
#define ATT_SMEM2 (4 * 17408 + 1024 + 64)

__global__ __launch_bounds__(256, 2) void attn_f16(
    const char* __restrict__ Kt, const char* __restrict__ Vt,
    const unsigned* __restrict__ Mk)
{
    extern __shared__ __align__(16) char raw[];
    char* sm = (char*)((((uintptr_t)raw) + 1023) & ~(uintptr_t)1023);
    const uint32_t sb = sptr(sm);
    const uint32_t barb = sb + 4 * ATT_STAGE2;

    const int t = threadIdx.x, lane = t & 31, wid = t >> 5;
    const int g = lane >> 2, q = lane & 3;
    const int b = blockIdx.z, h = blockIdx.y, e0 = blockIdx.x * 128;
    const int R = wid * 16;

    const unsigned* Qhw = (const unsigned*)(g_Qh + ((size_t)(b * N_EDGESC + e0 + R) * 512 + h * 64));
    unsigned qh[4][4];
#pragma unroll
    for (int ks = 0; ks < 4; ks++) {
        int o = 8 * ks + q;
        qh[ks][0] = Qhw[g * 256 + o];       qh[ks][1] = Qhw[(g + 8) * 256 + o];
        qh[ks][2] = Qhw[g * 256 + o + 4];   qh[ks][3] = Qhw[(g + 8) * 256 + o + 4];
    }

    if (t == 0) {
#pragma unroll
        for (int p = 0; p < 4; p++) MBAR_INIT(barb + 8 * p, 1);
    }
    __syncthreads();

    const char* Kb = Kt + (size_t)(b * N_HEADSC + h) * 64 * 8192;
    const char* Vb = Vt + (size_t)(b * N_HEADSC + h) * 64 * 8192;
    const unsigned* Mb = Mk + (size_t)b * 128 * 1024 + e0;

    const uint32_t laneXor = (uint32_t)((lane & 7) << 4);
    const uint32_t kRow = (uint32_t)(((lane & 7) + ((lane >> 4) & 1) * 8) * 128);
    const uint32_t kC   = (uint32_t)(((lane >> 3) & 1) * 16);
    const uint32_t vRow = (uint32_t)(((lane & 7) + ((lane >> 3) & 1) * 8) * 128);
    const uint32_t vC   = (uint32_t)((lane >> 4) * 16);

    float O[8][4];
#pragma unroll
    for (int nb = 0; nb < 8; nb++)
#pragma unroll
        for (int i = 0; i < 4; i++) O[nb][i] = 0.f;
    float lacc[4] = {0.f, 0.f, 0.f, 0.f};
    const unsigned ones2[2] = {0x3C003C00u, 0x3C003C00u};

    if (t == 0) {
#pragma unroll
        for (int p = 0; p < 3; p++) {
            const uint32_t s2 = sb + (uint32_t)p * ATT_STAGE2;
            MBAR_ARRIVE_TX(barb + 8 * p, 17408);
            bulkcp(s2,         Kb + (size_t)p * 8192, 8192, barb + 8 * p);
            bulkcp(s2 + 8192,  Vb + (size_t)p * 8192, 8192, barb + 8 * p);
            bulkcp(s2 + 16384, Mb + (size_t)p * 2048,        512, barb + 8 * p);
            bulkcp(s2 + 16896, Mb + (size_t)p * 2048 + 1024, 512, barb + 8 * p);
        }
    }

    for (int it4 = 0; it4 < 16; it4++) {
#pragma unroll
        for (int st = 0; st < 4; st++) {
            const int it = it4 * 4 + st;
            if (it + 3 < 64 && t == 0) {
                const int st2 = (st + 3) & 3;
                const uint32_t s2 = sb + (uint32_t)st2 * ATT_STAGE2;
                MBAR_ARRIVE_TX(barb + 8 * st2, 17408);
                bulkcp(s2,         Kb + (size_t)(it + 3) * 8192, 8192, barb + 8 * st2);
                bulkcp(s2 + 8192,  Vb + (size_t)(it + 3) * 8192, 8192, barb + 8 * st2);
                bulkcp(s2 + 16384, Mb + (size_t)(it + 3) * 2048,        512, barb + 8 * st2);
                bulkcp(s2 + 16896, Mb + (size_t)(it + 3) * 2048 + 1024, 512, barb + 8 * st2);
            }
            MBAR_WAIT(barb + 8 * st, (st < 3) ? (it4 & 1) : ((it4 + 1) & 1) ^ 1);

            const uint32_t stAddr = sb + (uint32_t)st * ATT_STAGE2;
            const unsigned* Mp = (const unsigned*)(sm + st * 17408 + 16384);

            float s[8][4];
#pragma unroll
            for (int nb = 0; nb < 8; nb++) {
                s[nb][0] = 0.f; s[nb][1] = 0.f; s[nb][2] = 0.f; s[nb][3] = 0.f;
            }
#pragma unroll
            for (int ks = 0; ks < 4; ks++) {
                const uint32_t colK = ((uint32_t)(ks * 32) + kC) ^ laneXor;
#pragma unroll
                for (int nbp = 0; nbp < 4; nbp++) {
                    unsigned bh[4];
                    LDSM4(bh[0], bh[1], bh[2], bh[3],
                          stAddr + (uint32_t)(nbp * 2048) + kRow + colK);
                    mma16(s[2 * nbp], qh[ks], bh);
                    mma16(s[2 * nbp + 1], qh[ks], bh + 2);
                }
            }

            const unsigned wA0 = Mp[R + g],     wA1 = Mp[128 + R + g];
            const unsigned wB0 = Mp[R + g + 8], wB1 = Mp[128 + R + g + 8];
            unsigned pa[4][4];
#pragma unroll
            for (int nb = 0; nb < 8; nb++) {
                const unsigned w0 = (nb < 4) ? wA0 : wA1;
                const unsigned w1 = (nb < 4) ? wB0 : wB1;
                const int c0 = (nb * 8 + 2 * q) & 31;
                unsigned u01 = cvt2(s[nb][0], s[nb][1]);
                unsigned u23 = cvt2(s[nb][2], s[nb][3]);
                asm("ex2.approx.f16x2 %0, %1;" : "=r"(u01) : "r"(u01));
                asm("ex2.approx.f16x2 %0, %1;" : "=r"(u23) : "r"(u23));
                unsigned mm0 = (((w0 >> c0) & 1u) ? 0xFFFFu : 0u) |
                               (((w0 >> (c0 + 1)) & 1u) ? 0xFFFF0000u : 0u);
                unsigned mm1 = (((w1 >> c0) & 1u) ? 0xFFFFu : 0u) |
                               (((w1 >> (c0 + 1)) & 1u) ? 0xFFFF0000u : 0u);
                u01 &= mm0;
                u23 &= mm1;
                const int jj = nb >> 1, o2 = (nb & 1) << 1;
                pa[jj][o2] = u01;
                pa[jj][o2 + 1] = u23;
            }

#pragma unroll
            for (int j = 0; j < 4; j++) {
                mma16(lacc, pa[j], ones2);
#pragma unroll
                for (int dbp = 0; dbp < 4; dbp++) {
                    const uint32_t colV = ((uint32_t)(dbp * 32) + vC) ^ laneXor;
                    unsigned bh[4];
                    LDSM4T(bh[0], bh[1], bh[2], bh[3],
                           stAddr + 8192 + (uint32_t)(j * 2048) + vRow + colV);
                    mma16(O[2 * dbp], pa[j], bh);
                    mma16(O[2 * dbp + 1], pa[j], bh + 2);
                }
            }
            __syncthreads();
        }
    }

    float inv0 = 1.f / lacc[0], inv1 = 1.f / lacc[2];
    size_t rw0 = ((size_t)(b * N_EDGESC + e0 + R + g) * 512 + h * 64) >> 1;
    size_t rw1 = rw0 + 8 * 256;
    unsigned* Ahw = (unsigned*)g_Ah;
#pragma unroll
    for (int nb = 0; nb < 8; nb++) {
        int cw = 4 * nb + q;
        Ahw[rw0 + cw] = cvt2(O[nb][0] * inv0, O[nb][1] * inv0);
        Ahw[rw1 + cw] = cvt2(O[nb][2] * inv1, O[nb][3] * inv1);
    }
}

// ---------------------------------------------------------------------------
extern "C" void kernel_launch(void* const* d_in, const int* in_sizes, int n_in,
                              void* d_out, int out_size) {
    (void)in_sizes; (void)n_in; (void)out_size;
    const float* queries = (const float*)d_in[0];
    const float* keys    = (const float*)d_in[1];
    const int*   inc     = (const int*)d_in[2];
    const float* Wq = (const float*)d_in[3];
    const float* bq = (const float*)d_in[4];
    const float* Wk = (const float*)d_in[5];
    const float* bk = (const float*)d_in[6];
    const float* Wv = (const float*)d_in[7];
    const float* bv = (const float*)d_in[8];
    const float* Wo = (const float*)d_in[9];
    const float* bo = (const float*)d_in[10];
    float* out = (float*)d_out;

    __half *qh, *kh, *Wqh, *Wkh, *Wvh, *Woh, *Qh, *Kh, *Vh, *Ah;
    unsigned* pM;
    cudaGetSymbolAddress((void**)&qh, g_qh);
    cudaGetSymbolAddress((void**)&kh, g_kh);
    cudaGetSymbolAddress((void**)&Wqh, g_Wqh);
    cudaGetSymbolAddress((void**)&Wkh, g_Wkh);
    cudaGetSymbolAddress((void**)&Wvh, g_Wvh);
    cudaGetSymbolAddress((void**)&Woh, g_Woh);
    cudaGetSymbolAddress((void**)&Qh, g_Qh);
    cudaGetSymbolAddress((void**)&Kh, g_Kh);
    cudaGetSymbolAddress((void**)&Vh, g_Vh);
    cudaGetSymbolAddress((void**)&Ah, g_Ah);
    cudaGetSymbolAddress((void**)&pM, g_mask);

    cudaFuncSetAttribute(gemm_qkv, cudaFuncAttributeMaxDynamicSharedMemorySize, GQ_SMEM);
    cudaFuncSetAttribute(gemm_o, cudaFuncAttributeMaxDynamicSharedMemorySize, GEMM_O_SMEM);
    cudaFuncSetAttribute(attn_f16, cudaFuncAttributeMaxDynamicSharedMemorySize, ATT_SMEM2);

    prep_kernel<<<PREP_BLOCKS, 256>>>(
        (const float4*)queries, (const float4*)keys,
        (const float4*)Wq, (const float4*)Wk, (const float4*)Wv, (const float4*)Wo,
        (const int4*)inc,
        (char*)qh, (char*)kh, (char*)Wqh, (char*)Wkh, (char*)Wvh,
        (uint2*)Woh, pM);

    gemm_qkv<<<dim3(4, 288), 256, GQ_SMEM>>>(
        (const char*)qh, (const char*)kh, (const char*)Wqh, (const char*)Wkh,
        (const char*)Wvh, bq, bk, bv, Qh, Kh, Vh);

    attn_f16<<<dim3(N_EDGESC / 128, N_HEADSC, BSC), 256, ATT_SMEM2>>>(
        (const char*)Kh, (const char*)Vh, pM);

    gemm_o<<<dim3(4, 32), 256, GEMM_O_SMEM>>>(Ah, Woh, bo, out);
}